// round 1
// baseline (speedup 1.0000x reference)
#include <cuda_runtime.h>

#define NS   32    // state dim n
#define MD   16    // input dim m
#define PD   32    // obs dim p
#define TLEN 200
#define PAD  33    // padded row stride for 32x32 shared matrices
#define AUGW 66    // augmented matrix row stride (64 cols + 2 pad)

__global__ __launch_bounds__(256, 2)
void kf_kernel(const float* __restrict__ Yg, const float* __restrict__ Ug,
               const float* __restrict__ maskg, const float* __restrict__ Ag,
               const float* __restrict__ Bmg, const float* __restrict__ Cg,
               const float* __restrict__ mu0g, const float* __restrict__ Sig0g,
               const float* __restrict__ Qg, const float* __restrict__ Rg,
               float* __restrict__ mf, float* __restrict__ Sf,
               float* __restrict__ mp, float* __restrict__ Sp)
{
    __shared__ float sA[32*PAD], sC[32*PAD], sR[32*PAD], sBm[32*MD];
    __shared__ float Sig[32*PAD], Spred[32*PAD], CS[32*PAD], Tmp[32*PAD], IKC[32*PAD];
    __shared__ float aug[32*AUGW];
    __shared__ float prow[64], fcol[32];
    __shared__ float mu[32], mupred[32], munew[32], rv[32], yv[32], uv[MD];
    __shared__ float mval;

    const int tid = threadIdx.x;
    const int b   = blockIdx.x;
    const int tx  = tid & 15;
    const int ty  = tid >> 4;
    const int i0  = ty, i1 = ty + 16, j0 = tx, j1 = tx + 16;

    // ---- load constants + initial state ----
    for (int e = tid; e < 32*32; e += 256) {
        int i = e >> 5, j = e & 31;
        sA [i*PAD+j] = Ag[e];
        sC [i*PAD+j] = Cg[e];
        sR [i*PAD+j] = Rg[e];
        Sig[i*PAD+j] = Sig0g[e];
    }
    for (int e = tid; e < 32*MD; e += 256) sBm[e] = Bmg[e];
    if (tid < 32) mu[tid] = mu0g[tid];
    __syncthreads();

    const long long btbase = (long long)b * TLEN;

    for (int t = 0; t < TLEN; ++t) {
        const long long bt = btbase + t;

        // ---- phase 0: stage per-step inputs ----
        if (tid < 32)        yv[tid]      = Yg[bt*PD + tid];
        else if (tid < 48)   uv[tid-32]   = Ug[bt*MD + (tid-32)];
        else if (tid == 48)  mval         = maskg[bt];

        // Tmp = A @ Sig   (uses previous-iter Sig; y/u loads overlap)
        {
            float a00=0.f,a01=0.f,a10=0.f,a11=0.f;
            #pragma unroll
            for (int k = 0; k < 32; ++k) {
                float x0 = sA[i0*PAD+k], x1 = sA[i1*PAD+k];
                float y0 = Sig[k*PAD+j0], y1 = Sig[k*PAD+j1];
                a00 += x0*y0; a01 += x0*y1; a10 += x1*y0; a11 += x1*y1;
            }
            Tmp[i0*PAD+j0]=a00; Tmp[i0*PAD+j1]=a01;
            Tmp[i1*PAD+j0]=a10; Tmp[i1*PAD+j1]=a11;
        }
        __syncthreads();

        // mu_pred = A mu + Bm u
        if (tid < 32) {
            float acc = 0.f;
            #pragma unroll
            for (int j = 0; j < 32; ++j) acc += sA[tid*PAD+j]*mu[j];
            #pragma unroll
            for (int j = 0; j < MD; ++j) acc += sBm[tid*MD+j]*uv[j];
            mupred[tid] = acc;
        }
        // Spred = Tmp @ A^T + Q
        {
            float a00=0.f,a01=0.f,a10=0.f,a11=0.f;
            #pragma unroll
            for (int k = 0; k < 32; ++k) {
                float x0 = Tmp[i0*PAD+k], x1 = Tmp[i1*PAD+k];
                float y0 = sA[j0*PAD+k],  y1 = sA[j1*PAD+k];
                a00 += x0*y0; a01 += x0*y1; a10 += x1*y0; a11 += x1*y1;
            }
            Spred[i0*PAD+j0] = a00 + __ldg(&Qg[i0*32+j0]);
            Spred[i0*PAD+j1] = a01 + __ldg(&Qg[i0*32+j1]);
            Spred[i1*PAD+j0] = a10 + __ldg(&Qg[i1*32+j0]);
            Spred[i1*PAD+j1] = a11 + __ldg(&Qg[i1*32+j1]);
        }
        __syncthreads();

        // r = y - C mu_pred
        if (tid < 32) {
            float acc = yv[tid];
            #pragma unroll
            for (int j = 0; j < 32; ++j) acc -= sC[tid*PAD+j]*mupred[j];
            rv[tid] = acc;
        }
        // CS = C @ Spred  (this is also PCT^T, the solve RHS)
        {
            float a00=0.f,a01=0.f,a10=0.f,a11=0.f;
            #pragma unroll
            for (int k = 0; k < 32; ++k) {
                float x0 = sC[i0*PAD+k], x1 = sC[i1*PAD+k];
                float y0 = Spred[k*PAD+j0], y1 = Spred[k*PAD+j1];
                a00 += x0*y0; a01 += x0*y1; a10 += x1*y0; a11 += x1*y1;
            }
            CS[i0*PAD+j0]=a00; CS[i0*PAD+j1]=a01;
            CS[i1*PAD+j0]=a10; CS[i1*PAD+j1]=a11;
        }
        // write predicted outputs (Spred final since last sync)
        {
            float* dstS = Sp + bt*1024;
            #pragma unroll
            for (int s = 0; s < 4; ++s) {
                int e = tid + 256*s;
                dstS[e] = Spred[(e>>5)*PAD + (e&31)];
            }
            if (tid < 32) (mp + bt*32)[tid] = mupred[tid];
        }
        __syncthreads();

        // Sraw = CS @ C^T + R  -> Tmp
        {
            float a00=0.f,a01=0.f,a10=0.f,a11=0.f;
            #pragma unroll
            for (int k = 0; k < 32; ++k) {
                float x0 = CS[i0*PAD+k], x1 = CS[i1*PAD+k];
                float y0 = sC[j0*PAD+k], y1 = sC[j1*PAD+k];
                a00 += x0*y0; a01 += x0*y1; a10 += x1*y0; a11 += x1*y1;
            }
            Tmp[i0*PAD+j0] = a00 + sR[i0*PAD+j0];
            Tmp[i0*PAD+j1] = a01 + sR[i0*PAD+j1];
            Tmp[i1*PAD+j0] = a10 + sR[i1*PAD+j0];
            Tmp[i1*PAD+j1] = a11 + sR[i1*PAD+j1];
        }
        __syncthreads();

        // aug = [ sym(Sraw) | CS ]
        #pragma unroll
        for (int s = 0; s < 8; ++s) {
            int e = tid + 256*s;
            int i = e >> 6, j = e & 63;
            float v;
            if (j < 32) v = 0.5f*(Tmp[i*PAD+j] + Tmp[j*PAD+i]);
            else        v = CS[i*PAD + (j-32)];
            aug[i*AUGW+j] = v;
        }
        __syncthreads();

        // Gauss-Jordan (SPD, no pivoting): left half -> I, right half -> X = S^{-1} CS
        for (int k = 0; k < 32; ++k) {
            if (tid < 64) {
                float pinv = __frcp_rn(aug[k*AUGW+k]);
                prow[tid] = aug[k*AUGW+tid] * pinv;
            } else if (tid < 96) {
                int i = tid - 64;
                float v = aug[i*AUGW+k];
                fcol[i] = (i == k) ? (v - 1.0f) : v;   // makes row-k update a pure scale
            }
            __syncthreads();
            {
                int jb = tid & 63, ib = tid >> 6;
                float pj = prow[jb];
                #pragma unroll
                for (int s = 0; s < 8; ++s) {
                    int i = ib + 4*s;
                    aug[i*AUGW+jb] -= fcol[i] * pj;
                }
            }
            __syncthreads();
        }
        // now K[a][b] = mval * aug[b*AUGW+32+a]  (K = X^T, masked)

        // mu_new = mu_pred + K r
        if (tid < 32) {
            float acc = 0.f;
            #pragma unroll
            for (int p = 0; p < 32; ++p) acc += aug[p*AUGW+32+tid] * rv[p];
            munew[tid] = mupred[tid] + mval*acc;
        }
        // IKC = I - K C
        {
            float a00=0.f,a01=0.f,a10=0.f,a11=0.f;
            #pragma unroll
            for (int p = 0; p < 32; ++p) {
                float x0 = aug[p*AUGW+32+i0], x1 = aug[p*AUGW+32+i1];
                float y0 = sC[p*PAD+j0],      y1 = sC[p*PAD+j1];
                a00 += x0*y0; a01 += x0*y1; a10 += x1*y0; a11 += x1*y1;
            }
            IKC[i0*PAD+j0] = (i0==j0 ? 1.f : 0.f) - mval*a00;
            IKC[i0*PAD+j1] = (i0==j1 ? 1.f : 0.f) - mval*a01;
            IKC[i1*PAD+j0] = (i1==j0 ? 1.f : 0.f) - mval*a10;
            IKC[i1*PAD+j1] = (i1==j1 ? 1.f : 0.f) - mval*a11;
        }
        __syncthreads();

        // Tmp = IKC @ Spred ;  CS <- KR = K @ R (mask folded in)
        {
            float a00=0.f,a01=0.f,a10=0.f,a11=0.f;
            #pragma unroll
            for (int k = 0; k < 32; ++k) {
                float x0 = IKC[i0*PAD+k], x1 = IKC[i1*PAD+k];
                float y0 = Spred[k*PAD+j0], y1 = Spred[k*PAD+j1];
                a00 += x0*y0; a01 += x0*y1; a10 += x1*y0; a11 += x1*y1;
            }
            Tmp[i0*PAD+j0]=a00; Tmp[i0*PAD+j1]=a01;
            Tmp[i1*PAD+j0]=a10; Tmp[i1*PAD+j1]=a11;
        }
        {
            float a00=0.f,a01=0.f,a10=0.f,a11=0.f;
            #pragma unroll
            for (int p = 0; p < 32; ++p) {
                float x0 = aug[p*AUGW+32+i0], x1 = aug[p*AUGW+32+i1];
                float y0 = sR[p*PAD+j0],      y1 = sR[p*PAD+j1];
                a00 += x0*y0; a01 += x0*y1; a10 += x1*y0; a11 += x1*y1;
            }
            CS[i0*PAD+j0]=mval*a00; CS[i0*PAD+j1]=mval*a01;
            CS[i1*PAD+j0]=mval*a10; CS[i1*PAD+j1]=mval*a11;
        }
        __syncthreads();

        // raw = Tmp @ IKC^T + mval*(KR @ X)  -> Spred (already written out)
        {
            float a00=0.f,a01=0.f,a10=0.f,a11=0.f;
            #pragma unroll
            for (int k = 0; k < 32; ++k) {
                float x0 = Tmp[i0*PAD+k], x1 = Tmp[i1*PAD+k];
                float y0 = IKC[j0*PAD+k], y1 = IKC[j1*PAD+k];
                a00 += x0*y0; a01 += x0*y1; a10 += x1*y0; a11 += x1*y1;
            }
            float b00=0.f,b01=0.f,b10=0.f,b11=0.f;
            #pragma unroll
            for (int p = 0; p < 32; ++p) {
                float x0 = CS[i0*PAD+p], x1 = CS[i1*PAD+p];
                float y0 = aug[p*AUGW+32+j0], y1 = aug[p*AUGW+32+j1];
                b00 += x0*y0; b01 += x0*y1; b10 += x1*y0; b11 += x1*y1;
            }
            Spred[i0*PAD+j0] = a00 + mval*b00;
            Spred[i0*PAD+j1] = a01 + mval*b01;
            Spred[i1*PAD+j0] = a10 + mval*b10;
            Spred[i1*PAD+j1] = a11 + mval*b11;
        }
        __syncthreads();

        // Sig = sym(raw); write filtered outputs; commit mu
        {
            float* dstS = Sf + bt*1024;
            #pragma unroll
            for (int s = 0; s < 4; ++s) {
                int e = tid + 256*s;
                int i = e >> 5, j = e & 31;
                float v = 0.5f*(Spred[i*PAD+j] + Spred[j*PAD+i]);
                Sig[i*PAD+j] = v;
                dstS[e] = v;
            }
            if (tid < 32) {
                mu[tid] = munew[tid];
                (mf + bt*32)[tid] = munew[tid];
            }
        }
        __syncthreads();
    }
}

extern "C" void kernel_launch(void* const* d_in, const int* in_sizes, int n_in,
                              void* d_out, int out_size)
{
    const float* Y    = (const float*)d_in[0];
    const float* U    = (const float*)d_in[1];
    const float* mask = (const float*)d_in[2];
    const float* A    = (const float*)d_in[3];
    const float* Bm   = (const float*)d_in[4];
    const float* C    = (const float*)d_in[5];
    const float* mu0  = (const float*)d_in[6];
    const float* Sig0 = (const float*)d_in[7];
    const float* Q    = (const float*)d_in[8];
    const float* R    = (const float*)d_in[9];

    const int BT = in_sizes[2];          // B*T from mask
    const int B  = BT / TLEN;

    float* out = (float*)d_out;
    float* mf = out;
    float* Sf = mf + (long long)BT * NS;
    float* mp = Sf + (long long)BT * NS * NS;
    float* Sp = mp + (long long)BT * NS;

    kf_kernel<<<B, 256>>>(Y, U, mask, A, Bm, C, mu0, Sig0, Q, R, mf, Sf, mp, Sp);
}

// round 2
// speedup vs baseline: 2.9308x; 2.9308x over previous
#include <cuda_runtime.h>

#define TLEN 200
#define SP   36     // row stride (floats) for 32-wide shared matrices; 144B, 16B-aligned
#define BMP  20     // row stride for Bm (16 cols); 80B, 16B-aligned

// NN 32x32x32 matmul fragment: thread (ty, tx) computes out[ty][4tx..4tx+3].
// X read row-major (float4 along k), Y read row-major (float4 along j).
__device__ __forceinline__ float4 mm_nn(const float* __restrict__ X,
                                        const float* __restrict__ Y,
                                        int ty, int tx)
{
    float4 acc = {0.f, 0.f, 0.f, 0.f};
    #pragma unroll
    for (int k4 = 0; k4 < 8; ++k4) {
        float4 x = *(const float4*)(X + ty*SP + 4*k4);
        const float* yb = Y + (4*k4)*SP + 4*tx;
        float4 y0 = *(const float4*)(yb);
        float4 y1 = *(const float4*)(yb + SP);
        float4 y2 = *(const float4*)(yb + 2*SP);
        float4 y3 = *(const float4*)(yb + 3*SP);
        acc.x += x.x*y0.x; acc.y += x.x*y0.y; acc.z += x.x*y0.z; acc.w += x.x*y0.w;
        acc.x += x.y*y1.x; acc.y += x.y*y1.y; acc.z += x.y*y1.z; acc.w += x.y*y1.w;
        acc.x += x.z*y2.x; acc.y += x.z*y2.y; acc.z += x.z*y2.z; acc.w += x.z*y2.w;
        acc.x += x.w*y3.x; acc.y += x.w*y3.y; acc.z += x.w*y3.z; acc.w += x.w*y3.w;
    }
    return acc;
}

__global__ __launch_bounds__(256, 2)
void kf_kernel(const float* __restrict__ Yg, const float* __restrict__ Ug,
               const float* __restrict__ maskg, const float* __restrict__ Ag,
               const float* __restrict__ Bmg, const float* __restrict__ Cg,
               const float* __restrict__ mu0g, const float* __restrict__ Sig0g,
               const float* __restrict__ Qg, const float* __restrict__ Rg,
               float* __restrict__ mf, float* __restrict__ Sf,
               float* __restrict__ mp, float* __restrict__ Sp)
{
    __shared__ __align__(16) float sA [32*SP], sAT[32*SP], sC [32*SP], sCT[32*SP];
    __shared__ __align__(16) float Sig[32*SP], Spr[32*SP], CS [32*SP], Tm [32*SP], Km [32*SP];
    __shared__ __align__(16) float sBm[32*BMP];
    __shared__ __align__(16) float prow[2][68];   // pivot row snapshot (unscaled), ping-pong
    __shared__ __align__(16) float fcol[2][32];   // pivot column snapshot, ping-pong
    __shared__ __align__(16) float mu[32], mupr[32], munew[32], rv[32], yv[32], uv[16];
    __shared__ float mvals;

    const int tid  = threadIdx.x;
    const int b    = blockIdx.x;
    const int tx   = tid & 7;     // matmul: 8 col-groups of 4
    const int ty   = tid >> 3;    // matmul: 32 rows
    const int scol = tid & 15;    // solve: 16 float4 columns (64 cols)
    const int srow = tid >> 4;    // solve: rows srow and srow+16

    // ---- one-time setup: constants (A, A^T, C, C^T, Bm), initial state ----
    for (int e = tid; e < 1024; e += 256) {
        int i = e >> 5, j = e & 31;
        float a = Ag[e], c = Cg[e];
        sA [i*SP+j] = a;  sAT[j*SP+i] = a;
        sC [i*SP+j] = c;  sCT[j*SP+i] = c;
        Sig[i*SP+j] = Sig0g[e];
    }
    for (int e = tid; e < 512; e += 256) { int i = e >> 4, j = e & 15; sBm[i*BMP+j] = Bmg[e]; }
    if (tid < 32) mu[tid] = mu0g[tid];
    __syncthreads();

    const long long btb = (long long)b * TLEN;

    for (int t = 0; t < TLEN; ++t) {
        const long long bt = btb + t;

        // ---- phase 1: stage inputs; Tm = A @ Sig ----
        if (tid < 32)        yv[tid]    = Yg[bt*32 + tid];
        else if (tid < 48)   uv[tid-32] = Ug[bt*16 + (tid-32)];
        else if (tid == 48)  mvals      = maskg[bt];
        {
            float4 acc = mm_nn(sA, Sig, ty, tx);
            *(float4*)(Tm + ty*SP + 4*tx) = acc;
        }
        __syncthreads();

        // ---- phase 2: Spr = Tm @ A^T + Q (NN via sAT); mu_pred; write Sp, mp ----
        {
            float4 acc = mm_nn(Tm, sAT, ty, tx);
            float4 q4  = __ldg((const float4*)(Qg + ty*32 + 4*tx));
            acc.x += q4.x; acc.y += q4.y; acc.z += q4.z; acc.w += q4.w;
            *(float4*)(Spr + ty*SP + 4*tx) = acc;
            *(float4*)(Sp + bt*1024 + ty*32 + 4*tx) = acc;
        }
        if (tid < 32) {
            float acc = 0.f;
            #pragma unroll
            for (int c = 0; c < 8; ++c) {
                float4 a = *(const float4*)(sA + tid*SP + 4*c);
                float4 m = *(const float4*)(mu + 4*c);
                acc += a.x*m.x + a.y*m.y + a.z*m.z + a.w*m.w;
            }
            #pragma unroll
            for (int c = 0; c < 4; ++c) {
                float4 a = *(const float4*)(sBm + tid*BMP + 4*c);
                float4 m = *(const float4*)(uv + 4*c);
                acc += a.x*m.x + a.y*m.y + a.z*m.z + a.w*m.w;
            }
            mupr[tid] = acc;
            mp[bt*32 + tid] = acc;
        }
        __syncthreads();

        // ---- phase 3: CS = C @ Spr; r = y - C mu_pred ----
        {
            float4 acc = mm_nn(sC, Spr, ty, tx);
            *(float4*)(CS + ty*SP + 4*tx) = acc;
        }
        if (tid < 32) {
            float acc = yv[tid];
            #pragma unroll
            for (int c = 0; c < 8; ++c) {
                float4 a = *(const float4*)(sC + tid*SP + 4*c);
                float4 m = *(const float4*)(mupr + 4*c);
                acc -= a.x*m.x + a.y*m.y + a.z*m.z + a.w*m.w;
            }
            rv[tid] = acc;
        }
        __syncthreads();

        // ---- phase 4: Tm = CS @ C^T (raw S before sym+R) ----
        {
            float4 acc = mm_nn(CS, sCT, ty, tx);
            *(float4*)(Tm + ty*SP + 4*tx) = acc;
        }
        __syncthreads();

        // ---- phase 5: load augmented [ sym(Tm)+R | CS ] into registers; seed pivot-0 snapshot ----
        float4 e0, e1;
        if (scol < 8) {
            const int j0 = 4*scol;
            float4 t0 = *(const float4*)(Tm + srow*SP + j0);
            float4 t1 = *(const float4*)(Tm + (srow+16)*SP + j0);
            float4 r0 = __ldg((const float4*)(Rg + srow*32 + j0));
            float4 r1 = __ldg((const float4*)(Rg + (srow+16)*32 + j0));
            e0.x = 0.5f*(t0.x + Tm[(j0+0)*SP + srow]) + r0.x;
            e0.y = 0.5f*(t0.y + Tm[(j0+1)*SP + srow]) + r0.y;
            e0.z = 0.5f*(t0.z + Tm[(j0+2)*SP + srow]) + r0.z;
            e0.w = 0.5f*(t0.w + Tm[(j0+3)*SP + srow]) + r0.w;
            e1.x = 0.5f*(t1.x + Tm[(j0+0)*SP + srow+16]) + r1.x;
            e1.y = 0.5f*(t1.y + Tm[(j0+1)*SP + srow+16]) + r1.y;
            e1.z = 0.5f*(t1.z + Tm[(j0+2)*SP + srow+16]) + r1.z;
            e1.w = 0.5f*(t1.w + Tm[(j0+3)*SP + srow+16]) + r1.w;
        } else {
            const int j0 = 4*(scol-8);
            e0 = *(const float4*)(CS + srow*SP + j0);
            e1 = *(const float4*)(CS + (srow+16)*SP + j0);
        }
        if (srow == 0) *(float4*)(&prow[0][4*scol]) = e0;
        if (scol == 0) { fcol[0][srow] = e0.x; fcol[0][srow+16] = e1.x; }
        __syncthreads();

        // ---- phase 6: register-resident Gauss-Jordan, 1 barrier/pivot ----
        // update: v -= g_i * prow_k[j];  g_i = (i==k) ? 1-1/d : v[i][k]/d  (prow unscaled)
        #pragma unroll
        for (int k = 0; k < 32; ++k) {
            const int cur = k & 1, nxt = cur ^ 1;
            const float pinv = __frcp_rn(prow[cur][k]);
            const float4 p4 = *(const float4*)(&prow[cur][4*scol]);
            const float g0 = (srow      == k) ? (1.0f - pinv) : fcol[cur][srow]      * pinv;
            const float g1 = (srow + 16 == k) ? (1.0f - pinv) : fcol[cur][srow + 16] * pinv;
            e0.x -= g0*p4.x; e0.y -= g0*p4.y; e0.z -= g0*p4.z; e0.w -= g0*p4.w;
            e1.x -= g1*p4.x; e1.y -= g1*p4.y; e1.z -= g1*p4.z; e1.w -= g1*p4.w;
            if (k < 31) {
                const int kn = k + 1;
                if (scol == (kn >> 2)) {            // snapshot column kn
                    const int cmp = kn & 3;         // static (loop unrolled)
                    fcol[nxt][srow]      = (cmp==0)?e0.x:(cmp==1)?e0.y:(cmp==2)?e0.z:e0.w;
                    fcol[nxt][srow + 16] = (cmp==0)?e1.x:(cmp==1)?e1.y:(cmp==2)?e1.z:e1.w;
                }
                if (srow == kn)      *(float4*)(&prow[nxt][4*scol]) = e0;   // snapshot row kn
                if (srow + 16 == kn) *(float4*)(&prow[nxt][4*scol]) = e1;
            }
            __syncthreads();
        }

        // ---- phase 7: K = mval * X^T  (X = right half, in registers) ----
        {
            const float mv = mvals;
            if (scol >= 8) {
                const int a0 = 4*(scol-8);
                Km[(a0+0)*SP + srow] = mv*e0.x;
                Km[(a0+1)*SP + srow] = mv*e0.y;
                Km[(a0+2)*SP + srow] = mv*e0.z;
                Km[(a0+3)*SP + srow] = mv*e0.w;
                Km[(a0+0)*SP + srow+16] = mv*e1.x;
                Km[(a0+1)*SP + srow+16] = mv*e1.y;
                Km[(a0+2)*SP + srow+16] = mv*e1.z;
                Km[(a0+3)*SP + srow+16] = mv*e1.w;
            }
        }
        __syncthreads();

        // ---- phase 8: Tm = Spr - K @ CS (unsym Sigma_new); mu_new = mu_pred + K r ----
        {
            float4 acc = mm_nn(Km, CS, ty, tx);
            float4 sp4 = *(const float4*)(Spr + ty*SP + 4*tx);
            float4 v;
            v.x = sp4.x - acc.x; v.y = sp4.y - acc.y;
            v.z = sp4.z - acc.z; v.w = sp4.w - acc.w;
            *(float4*)(Tm + ty*SP + 4*tx) = v;
        }
        if (tid < 32) {
            float acc = 0.f;
            #pragma unroll
            for (int c = 0; c < 8; ++c) {
                float4 a = *(const float4*)(Km + tid*SP + 4*c);
                float4 m = *(const float4*)(rv + 4*c);
                acc += a.x*m.x + a.y*m.y + a.z*m.z + a.w*m.w;
            }
            munew[tid] = mupr[tid] + acc;
        }
        __syncthreads();

        // ---- phase 9: Sig = sym(Tm); write Sf, mf; commit mu ----
        {
            float4 v = *(const float4*)(Tm + ty*SP + 4*tx);
            float t0 = Tm[(4*tx+0)*SP + ty];
            float t1 = Tm[(4*tx+1)*SP + ty];
            float t2 = Tm[(4*tx+2)*SP + ty];
            float t3 = Tm[(4*tx+3)*SP + ty];
            float4 s;
            s.x = 0.5f*(v.x + t0); s.y = 0.5f*(v.y + t1);
            s.z = 0.5f*(v.z + t2); s.w = 0.5f*(v.w + t3);
            *(float4*)(Sig + ty*SP + 4*tx) = s;
            *(float4*)(Sf + bt*1024 + ty*32 + 4*tx) = s;
        }
        if (tid < 32) {
            mu[tid] = munew[tid];
            mf[bt*32 + tid] = munew[tid];
        }
        __syncthreads();
    }
}

extern "C" void kernel_launch(void* const* d_in, const int* in_sizes, int n_in,
                              void* d_out, int out_size)
{
    const float* Y    = (const float*)d_in[0];
    const float* U    = (const float*)d_in[1];
    const float* mask = (const float*)d_in[2];
    const float* A    = (const float*)d_in[3];
    const float* Bm   = (const float*)d_in[4];
    const float* C    = (const float*)d_in[5];
    const float* mu0  = (const float*)d_in[6];
    const float* Sig0 = (const float*)d_in[7];
    const float* Q    = (const float*)d_in[8];
    const float* R    = (const float*)d_in[9];

    const int BT = in_sizes[2];          // B*T from mask
    const int B  = BT / TLEN;

    float* out = (float*)d_out;
    float* mf = out;
    float* Sf = mf + (long long)BT * 32;
    float* mp = Sf + (long long)BT * 1024;
    float* Sp = mp + (long long)BT * 32;

    kf_kernel<<<B, 256>>>(Y, U, mask, A, Bm, C, mu0, Sig0, Q, R, mf, Sf, mp, Sp);
}

// round 3
// speedup vs baseline: 4.2784x; 1.4598x over previous
#include <cuda_runtime.h>

#define TLEN 200
#define SP   36     // row stride (floats) for 32-wide shared matrices
#define BMP  20     // row stride for Bm (16 cols)

#define DUP2(d,s)   asm("mov.b64 %0, {%1,%1};" : "=l"(d) : "f"(s))
#define FMA2(d,a,b) asm("fma.rn.f32x2 %0, %1, %2, %0;" : "+l"(d) : "l"(a), "l"(b))
#define ADD2(d,a)   asm("add.rn.f32x2 %0, %0, %1;" : "+l"(d) : "l"(a))

__device__ __forceinline__ float2 lo2(unsigned long long u) {
    float2 f;
    f.x = __uint_as_float((unsigned)u);
    f.y = __uint_as_float((unsigned)(u >> 32));
    return f;
}

// NN 32x32x32 matmul, thread computes rows (ty, ty+16) x cols [4tx,4tx+4) via f32x2.
__device__ __forceinline__ void mm24(const float* __restrict__ X,
                                     const float* __restrict__ Y,
                                     int ty, int tx,
                                     unsigned long long& a01, unsigned long long& a23,
                                     unsigned long long& b01, unsigned long long& b23)
{
    a01 = a23 = b01 = b23 = 0ULL;
    #pragma unroll
    for (int k4 = 0; k4 < 8; ++k4) {
        float4 x0 = *(const float4*)(X + ty*SP + 4*k4);
        float4 x1 = *(const float4*)(X + (ty+16)*SP + 4*k4);
        #pragma unroll
        for (int kk = 0; kk < 4; ++kk) {
            ulonglong2 y2 = *(const ulonglong2*)(Y + (4*k4+kk)*SP + 4*tx);
            float xs0 = (kk==0)?x0.x:(kk==1)?x0.y:(kk==2)?x0.z:x0.w;
            float xs1 = (kk==0)?x1.x:(kk==1)?x1.y:(kk==2)?x1.z:x1.w;
            unsigned long long xd0, xd1;
            DUP2(xd0, xs0);
            DUP2(xd1, xs1);
            FMA2(a01, xd0, y2.x);
            FMA2(a23, xd0, y2.y);
            FMA2(b01, xd1, y2.x);
            FMA2(b23, xd1, y2.y);
        }
    }
}

__global__ __launch_bounds__(256, 2)
void kf_kernel(const float* __restrict__ Yg, const float* __restrict__ Ug,
               const float* __restrict__ maskg, const float* __restrict__ Ag,
               const float* __restrict__ Bmg, const float* __restrict__ Cg,
               const float* __restrict__ mu0g, const float* __restrict__ Sig0g,
               const float* __restrict__ Qg, const float* __restrict__ Rg,
               float* __restrict__ mf, float* __restrict__ Sf,
               float* __restrict__ mp, float* __restrict__ Sp)
{
    __shared__ __align__(16) float sA [32*SP], sAT[32*SP], sC [32*SP], sCT[32*SP];
    __shared__ __align__(16) float Sig[32*SP], Spr[32*SP], CS [32*SP], Tm [32*SP], Km [32*SP];
    __shared__ __align__(16) float sBm[32*BMP];
    __shared__ __align__(16) float prowS[2][2][68];   // two pivot-row snapshots, ping-pong
    __shared__ __align__(16) float fcolS[2][2][34];   // two pivot-col snapshots, ping-pong
    __shared__ __align__(16) float mu[32], mupr[32], rv[32], yv[32], uv[16];
    __shared__ float mvals;

    const int tid  = threadIdx.x;
    const int b    = blockIdx.x;
    const int mtx  = tid & 7;      // matmul cols (4 per thread), warps 0-3 only
    const int mty  = tid >> 3;     // matmul rows (mty, mty+16), valid for tid<128
    const int scol = tid & 15;     // solve: 16 float4-column groups (64 cols)
    const int srow = tid >> 4;     // solve: rows srow, srow+16

    // ---- one-time setup ----
    for (int e = tid; e < 1024; e += 256) {
        int i = e >> 5, j = e & 31;
        float a = Ag[e], c = Cg[e];
        sA [i*SP+j] = a;  sAT[j*SP+i] = a;
        sC [i*SP+j] = c;  sCT[j*SP+i] = c;
        Sig[i*SP+j] = Sig0g[e];
    }
    for (int e = tid; e < 512; e += 256) { int i = e >> 4, j = e & 15; sBm[i*BMP+j] = Bmg[e]; }
    if (tid < 32) mu[tid] = mu0g[tid];

    // hoisted constants: Q rows (matmul threads), R rows (solve threads, scol<8)
    ulonglong2 qa = make_ulonglong2(0,0), qb = make_ulonglong2(0,0);
    if (tid < 128) {
        qa = *(const ulonglong2*)(Qg + mty*32 + 4*mtx);
        qb = *(const ulonglong2*)(Qg + (mty+16)*32 + 4*mtx);
    }
    float4 rr0 = {0,0,0,0}, rr1 = {0,0,0,0};
    if (scol < 8) {
        rr0 = __ldg((const float4*)(Rg + srow*32 + 4*scol));
        rr1 = __ldg((const float4*)(Rg + (srow+16)*32 + 4*scol));
    }
    __syncthreads();

    const long long btb = (long long)b * TLEN;

    for (int t = 0; t < TLEN; ++t) {
        const long long bt = btb + t;
        float mun = 0.f;                      // carried from P8 to P9 (warp 7)

        // ---- P1: stage inputs (w5,w6); Tm = A @ Sig (w0-3) ----
        if (tid < 128) {
            unsigned long long a01,a23,b01,b23;
            mm24(sA, Sig, mty, mtx, a01,a23,b01,b23);
            *(ulonglong2*)(Tm + mty*SP + 4*mtx)      = make_ulonglong2(a01,a23);
            *(ulonglong2*)(Tm + (mty+16)*SP + 4*mtx) = make_ulonglong2(b01,b23);
        } else if (tid >= 224) {
            // idle
        } else if (tid >= 192) {
            int l = tid - 192;
            yv[l] = Yg[bt*32 + l];
        } else if (tid >= 160) {
            int l = tid - 160;
            if (l < 16) uv[l] = Ug[bt*16 + l];
            else if (l == 16) mvals = maskg[bt];
        }
        __syncthreads();

        // ---- P2: Spr = Tm @ A^T + Q (w0-3, write Sp); mu_pred (w7, write mp) ----
        if (tid < 128) {
            unsigned long long a01,a23,b01,b23;
            mm24(Tm, sAT, mty, mtx, a01,a23,b01,b23);
            ADD2(a01, qa.x); ADD2(a23, qa.y); ADD2(b01, qb.x); ADD2(b23, qb.y);
            *(ulonglong2*)(Spr + mty*SP + 4*mtx)      = make_ulonglong2(a01,a23);
            *(ulonglong2*)(Spr + (mty+16)*SP + 4*mtx) = make_ulonglong2(b01,b23);
            *(ulonglong2*)(Sp + bt*1024 + mty*32 + 4*mtx)      = make_ulonglong2(a01,a23);
            *(ulonglong2*)(Sp + bt*1024 + (mty+16)*32 + 4*mtx) = make_ulonglong2(b01,b23);
        } else if (tid >= 224) {
            int l = tid - 224;
            float acc = 0.f;
            #pragma unroll
            for (int c = 0; c < 8; ++c) {
                float4 a = *(const float4*)(sA + l*SP + 4*c);
                float4 m = *(const float4*)(mu + 4*c);
                acc += a.x*m.x + a.y*m.y + a.z*m.z + a.w*m.w;
            }
            #pragma unroll
            for (int c = 0; c < 4; ++c) {
                float4 a = *(const float4*)(sBm + l*BMP + 4*c);
                float4 m = *(const float4*)(uv + 4*c);
                acc += a.x*m.x + a.y*m.y + a.z*m.z + a.w*m.w;
            }
            mupr[l] = acc;
            mp[bt*32 + l] = acc;
        }
        __syncthreads();

        // ---- P3: CS = C @ Spr (w0-3); r = y - C mu_pred (w7) ----
        if (tid < 128) {
            unsigned long long a01,a23,b01,b23;
            mm24(sC, Spr, mty, mtx, a01,a23,b01,b23);
            *(ulonglong2*)(CS + mty*SP + 4*mtx)      = make_ulonglong2(a01,a23);
            *(ulonglong2*)(CS + (mty+16)*SP + 4*mtx) = make_ulonglong2(b01,b23);
        } else if (tid >= 224) {
            int l = tid - 224;
            float acc = yv[l];
            #pragma unroll
            for (int c = 0; c < 8; ++c) {
                float4 a = *(const float4*)(sC + l*SP + 4*c);
                float4 m = *(const float4*)(mupr + 4*c);
                acc -= a.x*m.x + a.y*m.y + a.z*m.z + a.w*m.w;
            }
            rv[l] = acc;
        }
        __syncthreads();

        // ---- P4: Tm = CS @ C^T (raw S) ----
        if (tid < 128) {
            unsigned long long a01,a23,b01,b23;
            mm24(CS, sCT, mty, mtx, a01,a23,b01,b23);
            *(ulonglong2*)(Tm + mty*SP + 4*mtx)      = make_ulonglong2(a01,a23);
            *(ulonglong2*)(Tm + (mty+16)*SP + 4*mtx) = make_ulonglong2(b01,b23);
        }
        __syncthreads();

        // ---- P5: augmented [ sym(Tm)+R | CS ] into registers; seed round-0 snapshots ----
        float4 e0, e1;
        if (scol < 8) {
            const int j0 = 4*scol;
            float4 t0 = *(const float4*)(Tm + srow*SP + j0);
            float4 t1 = *(const float4*)(Tm + (srow+16)*SP + j0);
            e0.x = 0.5f*(t0.x + Tm[(j0+0)*SP + srow]) + rr0.x;
            e0.y = 0.5f*(t0.y + Tm[(j0+1)*SP + srow]) + rr0.y;
            e0.z = 0.5f*(t0.z + Tm[(j0+2)*SP + srow]) + rr0.z;
            e0.w = 0.5f*(t0.w + Tm[(j0+3)*SP + srow]) + rr0.w;
            e1.x = 0.5f*(t1.x + Tm[(j0+0)*SP + srow+16]) + rr1.x;
            e1.y = 0.5f*(t1.y + Tm[(j0+1)*SP + srow+16]) + rr1.y;
            e1.z = 0.5f*(t1.z + Tm[(j0+2)*SP + srow+16]) + rr1.z;
            e1.w = 0.5f*(t1.w + Tm[(j0+3)*SP + srow+16]) + rr1.w;
        } else {
            const int j0 = 4*(scol-8);
            e0 = *(const float4*)(CS + srow*SP + j0);
            e1 = *(const float4*)(CS + (srow+16)*SP + j0);
        }
        if (srow == 0) *(float4*)(&prowS[0][0][4*scol]) = e0;
        if (srow == 1) *(float4*)(&prowS[0][1][4*scol]) = e0;
        if (scol == 0) {
            fcolS[0][0][srow]    = e0.x;  fcolS[0][1][srow]    = e0.y;
            fcolS[0][0][srow+16] = e1.x;  fcolS[0][1][srow+16] = e1.y;
        }
        __syncthreads();

        // ---- P6: paired-pivot Gauss-Jordan, 16 rounds, 1 barrier each ----
        #pragma unroll
        for (int r = 0; r < 16; ++r) {
            const int cur = r & 1, nxt = cur ^ 1;
            const int p0 = 2*r, p1 = 2*r + 1;
            float4 P0 = *(const float4*)(&prowS[cur][0][4*scol]);
            float4 P1 = *(const float4*)(&prowS[cur][1][4*scol]);
            float B00 = prowS[cur][0][p0], B01v = prowS[cur][0][p1];
            float B10 = prowS[cur][1][p0], B11v = prowS[cur][1][p1];
            float dinv = __frcp_rn(B00*B11v - B01v*B10);
            float i00 =  B11v*dinv, i01 = -B01v*dinv;
            float i10 = -B10 *dinv, i11 =  B00 *dinv;
            float4 W0, W1;
            W0.x = i00*P0.x + i01*P1.x;  W0.y = i00*P0.y + i01*P1.y;
            W0.z = i00*P0.z + i01*P1.z;  W0.w = i00*P0.w + i01*P1.w;
            W1.x = i10*P0.x + i11*P1.x;  W1.y = i10*P0.y + i11*P1.y;
            W1.z = i10*P0.z + i11*P1.z;  W1.w = i10*P0.w + i11*P1.w;
            float g00 = fcolS[cur][0][srow]      - ((srow    == p0) ? 1.f : 0.f);
            float g01 = fcolS[cur][1][srow]      - ((srow    == p1) ? 1.f : 0.f);
            float g10 = fcolS[cur][0][srow + 16] - ((srow+16 == p0) ? 1.f : 0.f);
            float g11 = fcolS[cur][1][srow + 16] - ((srow+16 == p1) ? 1.f : 0.f);
            e0.x -= g00*W0.x + g01*W1.x;  e0.y -= g00*W0.y + g01*W1.y;
            e0.z -= g00*W0.z + g01*W1.z;  e0.w -= g00*W0.w + g01*W1.w;
            e1.x -= g10*W0.x + g11*W1.x;  e1.y -= g10*W0.y + g11*W1.y;
            e1.z -= g10*W0.z + g11*W1.z;  e1.w -= g10*W0.w + g11*W1.w;
            if (r < 15) {
                const int q0 = p0 + 2, q1 = p0 + 3;
                const int cq = q0 >> 2, c0 = q0 & 3;  // q0,q1 share a float4 group
                if (srow      == q0) *(float4*)(&prowS[nxt][0][4*scol]) = e0;
                if (srow + 16 == q0) *(float4*)(&prowS[nxt][0][4*scol]) = e1;
                if (srow      == q1) *(float4*)(&prowS[nxt][1][4*scol]) = e0;
                if (srow + 16 == q1) *(float4*)(&prowS[nxt][1][4*scol]) = e1;
                if (scol == cq) {
                    fcolS[nxt][0][srow]      = (c0 == 0) ? e0.x : e0.z;
                    fcolS[nxt][1][srow]      = (c0 == 0) ? e0.y : e0.w;
                    fcolS[nxt][0][srow + 16] = (c0 == 0) ? e1.x : e1.z;
                    fcolS[nxt][1][srow + 16] = (c0 == 0) ? e1.y : e1.w;
                }
            }
            __syncthreads();
        }

        // ---- P7: K = mval * X^T into Km ----
        if (scol >= 8) {
            const float mv = mvals;
            const int a0 = 4*(scol-8);
            Km[(a0+0)*SP + srow]    = mv*e0.x;
            Km[(a0+1)*SP + srow]    = mv*e0.y;
            Km[(a0+2)*SP + srow]    = mv*e0.z;
            Km[(a0+3)*SP + srow]    = mv*e0.w;
            Km[(a0+0)*SP + srow+16] = mv*e1.x;
            Km[(a0+1)*SP + srow+16] = mv*e1.y;
            Km[(a0+2)*SP + srow+16] = mv*e1.z;
            Km[(a0+3)*SP + srow+16] = mv*e1.w;
        }
        __syncthreads();

        // ---- P8: Tm = Spr - K @ CS (w0-3); mu_new (w7, kept in register) ----
        if (tid < 128) {
            unsigned long long a01,a23,b01,b23;
            mm24(Km, CS, mty, mtx, a01,a23,b01,b23);
            float2 A01 = lo2(a01), A23 = lo2(a23), B01f = lo2(b01), B23f = lo2(b23);
            float4 s0 = *(const float4*)(Spr + mty*SP + 4*mtx);
            float4 s1 = *(const float4*)(Spr + (mty+16)*SP + 4*mtx);
            float4 o0 = { s0.x - A01.x,  s0.y - A01.y,  s0.z - A23.x,  s0.w - A23.y  };
            float4 o1 = { s1.x - B01f.x, s1.y - B01f.y, s1.z - B23f.x, s1.w - B23f.y };
            *(float4*)(Tm + mty*SP + 4*mtx)      = o0;
            *(float4*)(Tm + (mty+16)*SP + 4*mtx) = o1;
        } else if (tid >= 224) {
            int l = tid - 224;
            float acc = 0.f;
            #pragma unroll
            for (int c = 0; c < 8; ++c) {
                float4 a = *(const float4*)(Km + l*SP + 4*c);
                float4 m = *(const float4*)(rv + 4*c);
                acc += a.x*m.x + a.y*m.y + a.z*m.z + a.w*m.w;
            }
            mun = mupr[l] + acc;
        }
        __syncthreads();

        // ---- P9: Sig = sym(Tm), write Sf (w0-3); commit mu, write mf (w7) ----
        if (tid < 128) {
            const int j0 = 4*mtx;
            float4 v0 = *(const float4*)(Tm + mty*SP + j0);
            float4 v1 = *(const float4*)(Tm + (mty+16)*SP + j0);
            float4 s0, s1;
            s0.x = 0.5f*(v0.x + Tm[(j0+0)*SP + mty]);
            s0.y = 0.5f*(v0.y + Tm[(j0+1)*SP + mty]);
            s0.z = 0.5f*(v0.z + Tm[(j0+2)*SP + mty]);
            s0.w = 0.5f*(v0.w + Tm[(j0+3)*SP + mty]);
            s1.x = 0.5f*(v1.x + Tm[(j0+0)*SP + mty+16]);
            s1.y = 0.5f*(v1.y + Tm[(j0+1)*SP + mty+16]);
            s1.z = 0.5f*(v1.z + Tm[(j0+2)*SP + mty+16]);
            s1.w = 0.5f*(v1.w + Tm[(j0+3)*SP + mty+16]);
            *(float4*)(Sig + mty*SP + j0)      = s0;
            *(float4*)(Sig + (mty+16)*SP + j0) = s1;
            *(float4*)(Sf + bt*1024 + mty*32 + j0)      = s0;
            *(float4*)(Sf + bt*1024 + (mty+16)*32 + j0) = s1;
        } else if (tid >= 224) {
            int l = tid - 224;
            mu[l] = mun;
            mf[bt*32 + l] = mun;
        }
        __syncthreads();
    }
}

extern "C" void kernel_launch(void* const* d_in, const int* in_sizes, int n_in,
                              void* d_out, int out_size)
{
    const float* Y    = (const float*)d_in[0];
    const float* U    = (const float*)d_in[1];
    const float* mask = (const float*)d_in[2];
    const float* A    = (const float*)d_in[3];
    const float* Bm   = (const float*)d_in[4];
    const float* C    = (const float*)d_in[5];
    const float* mu0  = (const float*)d_in[6];
    const float* Sig0 = (const float*)d_in[7];
    const float* Q    = (const float*)d_in[8];
    const float* R    = (const float*)d_in[9];

    const int BT = in_sizes[2];          // B*T from mask
    const int B  = BT / TLEN;

    float* out = (float*)d_out;
    float* mf = out;
    float* Sf = mf + (long long)BT * 32;
    float* mp = Sf + (long long)BT * 1024;
    float* Sp = mp + (long long)BT * 32;

    kf_kernel<<<B, 256>>>(Y, U, mask, A, Bm, C, mu0, Sig0, Q, R, mf, Sf, mp, Sp);
}